// round 3
// baseline (speedup 1.0000x reference)
#include <cuda_runtime.h>
#include <math.h>

// Problem constants (fixed by the reference)
#define E_TOT   400000
#define NFEAT   256
#define NHID    256
#define NCLS    64
#define HSZ     32
#define NGRP    25000

#define TM      64      // edges per block
#define KT      16      // K-chunk staged in smem
#define NTHREADS 256

// ---------------- packed fp32x2 helpers (Blackwell FFMA2) ----------------
__device__ __forceinline__ unsigned long long ffma2(unsigned long long a,
                                                    unsigned long long b,
                                                    unsigned long long c) {
    unsigned long long d;
    asm("fma.rn.f32x2 %0, %1, %2, %3;" : "=l"(d) : "l"(a), "l"(b), "l"(c));
    return d;
}
__device__ __forceinline__ unsigned long long pack2(float x, float y) {
    unsigned long long d;
    asm("mov.b64 %0, {%1, %2};" : "=l"(d) : "f"(x), "f"(y));
    return d;
}
__device__ __forceinline__ float2 unpack2(unsigned long long v) {
    float2 r;
    asm("mov.b64 {%0, %1}, %2;" : "=f"(r.x), "=f"(r.y) : "l"(v));
    return r;
}

// ---------------- GEMM: sC[64][NOUT] = act(sA[64][256] @ Wg[256][NOUT]) ----
// Thread layout: ty = tid/32 -> 8 row-groups of 8 rows; tx = tid%32 -> NOUT/32
// cols per thread. Accumulators packed as f32x2 pairs along N.
template<int NOUT, bool RELU>
__device__ __forceinline__ void gemm_tile(const float* sA,
                                          const float* __restrict__ Wg,
                                          float* sW, float* sC, int tid)
{
    constexpr int CPT   = NOUT / 32;   // cols per thread (8 or 2)
    constexpr int PAIRS = CPT / 2;     // f32x2 pairs (4 or 1)
    const int tx = tid & 31;
    const int ty = tid >> 5;
    const int row0 = ty * 8;
    const int col0 = tx * CPT;

    unsigned long long acc[8][PAIRS];
#pragma unroll
    for (int i = 0; i < 8; i++)
#pragma unroll
        for (int p = 0; p < PAIRS; p++) acc[i][p] = 0ull;

    for (int k0 = 0; k0 < 256; k0 += KT) {
        __syncthreads();   // protect sW reuse + previous-stage epilogues
        // stage W[k0:k0+KT, :] into sW[KT][NOUT] (coalesced float4)
        constexpr int NF4 = KT * NOUT / 4;
#pragma unroll
        for (int idx = tid; idx < NF4; idx += NTHREADS) {
            int r  = idx / (NOUT / 4);
            int c4 = idx % (NOUT / 4);
            *(float4*)(sW + r * NOUT + c4 * 4) =
                *(const float4*)(Wg + (size_t)(k0 + r) * NOUT + c4 * 4);
        }
        __syncthreads();

#pragma unroll
        for (int kk = 0; kk < KT; kk += 4) {
            float4 a4[8];
#pragma unroll
            for (int i = 0; i < 8; i++)
                a4[i] = *(const float4*)(sA + (row0 + i) * 256 + k0 + kk);
#pragma unroll
            for (int dk = 0; dk < 4; dk++) {
                unsigned long long bv[PAIRS];
#pragma unroll
                for (int p = 0; p < PAIRS; p++)
                    bv[p] = *(const unsigned long long*)(sW + (kk + dk) * NOUT + col0 + 2 * p);
#pragma unroll
                for (int i = 0; i < 8; i++) {
                    float a = ((const float*)(&a4[i]))[dk];
                    unsigned long long a2 = pack2(a, a);
#pragma unroll
                    for (int p = 0; p < PAIRS; p++)
                        acc[i][p] = ffma2(a2, bv[p], acc[i][p]);
                }
            }
        }
    }

    // epilogue (no trailing sync needed; next stage syncs before reading)
#pragma unroll
    for (int i = 0; i < 8; i++) {
#pragma unroll
        for (int p = 0; p < PAIRS; p++) {
            float2 v = unpack2(acc[i][p]);
            if (RELU) { v.x = fmaxf(v.x, 0.f); v.y = fmaxf(v.y, 0.f); }
            sC[(row0 + i) * NOUT + col0 + 2 * p]     = v.x;
            sC[(row0 + i) * NOUT + col0 + 2 * p + 1] = v.y;
        }
    }
}

// ---------------- full 3-layer MLP for a 64-edge tile ----------------
__device__ __forceinline__ void mlp_tile(const float* __restrict__ Xg,
                                         const float* __restrict__ W0,
                                         const float* __restrict__ W1,
                                         const float* __restrict__ W2,
                                         float* sA, float* sB, float* sW,
                                         float* sOut, int tid, int e0)
{
    __syncthreads();   // sA may still be read by the previous stage
    // load X tile [64][256] into sA
#pragma unroll
    for (int i = 0; i < 16; i++) {
        int lin = tid + i * NTHREADS;      // float4 index 0..4095
        int r   = lin >> 6;
        int c4  = lin & 63;
        *(float4*)(sA + r * 256 + c4 * 4) =
            *(const float4*)(Xg + (size_t)(e0 + r) * 256 + c4 * 4);
    }
    gemm_tile<256, true >(sA, W0, sW, sB,   tid);  // h0 = relu(X @ W0)
    gemm_tile<256, true >(sB, W1, sW, sA,   tid);  // h1 = relu(h0 @ W1)
    gemm_tile< 64, false>(sA, W2, sW, sOut, tid);  // x  = h1 @ W2
}

// ---------------- main fused kernel ----------------
__global__ void __launch_bounds__(NTHREADS, 1)
gnn_attn_kernel(const float* __restrict__ src,  const float* __restrict__ nbr,
                const float* __restrict__ ppr,  const int*   __restrict__ pidx,
                const float* __restrict__ W0,   const float* __restrict__ W1,
                const float* __restrict__ W2,   const float* __restrict__ Wqk,
                const float* __restrict__ Wk,   float* __restrict__ out)
{
    extern __shared__ float smem[];
    float* sA   = smem;               // 64*256
    float* sB   = sA  + 64 * 256;     // 64*256
    float* sW   = sB  + 64 * 256;     // 16*256
    float* sXs  = sW  + KT * 256;     // 64*64
    float* sXn  = sXs + 64 * 64;      // 64*64
    float* sQ   = sXn + 64 * 64;      // 64*32
    float* sK   = sQ  + 64 * 32;      // 64*32
    float* sWq  = sK  + 64 * 32;      // 64*32
    float* sWk  = sWq + 64 * 32;      // 64*32
    float* sEw  = sWk + 64 * 32;      // 64
    int*   sGid = (int*)(sEw + 64);   // 64

    const int tid = threadIdx.x;
    const int e0  = blockIdx.x * TM;

    // stage attention weights once per block
    for (int i = tid; i < NCLS * HSZ; i += NTHREADS) {
        sWq[i] = Wqk[i];
        sWk[i] = Wk[i];
    }

    mlp_tile(src, W0, W1, W2, sA, sB, sW, sXs, tid, e0);
    mlp_tile(nbr, W0, W1, W2, sA, sB, sW, sXn, tid, e0);
    __syncthreads();

    // q = xs @ Wqk, k = xn @ Wk   ([64,64] @ [64,32])
    for (int t = tid; t < TM * HSZ; t += NTHREADS) {
        int e = t >> 5, h = t & 31;
        float aq = 0.f, ak = 0.f;
#pragma unroll
        for (int c = 0; c < NCLS; c++) {
            aq += sXs[e * NCLS + c] * sWq[c * HSZ + h];
            ak += sXn[e * NCLS + c] * sWk[c * HSZ + h];
        }
        sQ[t] = aq;
        sK[t] = ak;
    }
    __syncthreads();

    // e_attn = sigmoid(q . k), fold in ppr
    if (tid < TM) {
        float s = 0.f;
#pragma unroll
        for (int h = 0; h < HSZ; h++) s += sQ[tid * HSZ + h] * sK[tid * HSZ + h];
        float sig = 1.f / (1.f + expf(-s));
        sEw[tid]  = sig * ppr[e0 + tid];
        sGid[tid] = pidx[e0 + tid];
    }
    __syncthreads();

    // segmented reduction: ppr_idx is sorted, so runs are contiguous.
    // 4 edge-strips x 64 cols; run-length compress -> few atomics per block.
    const int col  = tid & 63;
    const int part = tid >> 6;
    const int base = part * 16;
    float acc = 0.f;
    int prev = sGid[base];
#pragma unroll
    for (int i = 0; i < 16; i++) {
        int g = sGid[base + i];
        if (g != prev) {
            atomicAdd(out + (size_t)prev * NCLS + col, acc);
            acc = 0.f;
            prev = g;
        }
        acc += sXn[(base + i) * NCLS + col] * sEw[base + i];
    }
    atomicAdd(out + (size_t)prev * NCLS + col, acc);
}

__global__ void zero_out_kernel(float* __restrict__ out, int n) {
    int i = blockIdx.x * blockDim.x + threadIdx.x;
    if (i < n) out[i] = 0.f;
}

// ---------------- launch ----------------
extern "C" void kernel_launch(void* const* d_in, const int* in_sizes, int n_in,
                              void* d_out, int out_size)
{
    const float* src  = (const float*)d_in[0];   // source_attr [E,256]
    const float* nbr  = (const float*)d_in[1];   // neighbor_attr [E,256]
    const float* ppr  = (const float*)d_in[2];   // ppr_scores [E]
    const int*   pidx = (const int*)  d_in[3];   // ppr_idx [E] (sorted)
    // d_in[4] = neighbor_idx (unused by the reference)
    const float* W0   = (const float*)d_in[5];   // [256,256]
    const float* W1   = (const float*)d_in[6];   // [256,256]
    const float* W2   = (const float*)d_in[7];   // [256,64]
    const float* Wqk  = (const float*)d_in[8];   // [64,32]
    const float* Wk   = (const float*)d_in[9];   // [64,32]
    float* out = (float*)d_out;

    // smem: 2*64*256 + 16*256 + 2*64*64 + 4*64*32 + 128 floats
    const int smem_floats = 2 * 64 * 256 + KT * 256 + 2 * 64 * 64 + 4 * 64 * 32 + 128;
    const int smem_bytes  = smem_floats * (int)sizeof(float);  // 213,504 B
    cudaFuncSetAttribute(gnn_attn_kernel,
                         cudaFuncAttributeMaxDynamicSharedMemorySize, smem_bytes);

    zero_out_kernel<<<(out_size + 255) / 256, 256>>>(out, out_size);

    const int nblk = E_TOT / TM;   // 400000 / 64 = 6250
    gnn_attn_kernel<<<nblk, NTHREADS, smem_bytes>>>(
        src, nbr, ppr, pidx, W0, W1, W2, Wqk, Wk, out);
}

// round 5
// speedup vs baseline: 2.2170x; 2.2170x over previous
#include <cuda_runtime.h>
#include <cuda_bf16.h>
#include <math.h>
#include <stdint.h>

// ---------------- problem constants ----------------
#define E_TOT   400000
#define TILE    128
#define NBLK    (E_TOT / TILE)   // 3125
#define NCLS    64
#define HSZ     32
#define NTHREADS 512

// ---------------- smem byte offsets (from 1024-aligned base) -------------
#define OFF_AH   0u         // A hi  : 128 rows x 512B
#define OFF_AL   65536u     // A lo
#define OFF_B0   131072u    // B buf0: 32KB (hi 16KB + lo 16KB)
#define OFF_B1   163840u    // B buf1
#define OFF_Q    196608u    // q f32 [128][33]
#define OFF_EW   213504u    // ew f32 [128]
#define OFF_GID  214016u    // gid int [128]
#define OFF_KSM  131072u    // k f32 [128][33]  (alias over B0, used post-GEMM)
#define OFF_WSM  148480u    // x_n f32 [128][65] (alias, used post-GEMM)
#define SMEM_REQ (214528u + 1024u)

// ---------------- pre-split, pre-swizzled weights in global --------------
// image layout per matrix (B[n][k] = W[k][n]): 8 chunks (Kc=32);
// byte pos = chunk*N*64 + n*64 + ((kk*2) ^ (((n>>1)&3)<<4))
__device__ unsigned short gB0h[65536], gB0l[65536];   // layer0, N=256
__device__ unsigned short gB1h[65536], gB1l[65536];   // layer1, N=256
__device__ unsigned short gBfh[32768], gBfl[32768];   // finals, N=128:
// cols 0..31 = W2@Wqk, 32..95 = W2, 96..127 = W2@Wk

// ---------------- small helpers ----------------
__device__ __forceinline__ uint32_t smem_u32(const void* p) {
    uint32_t a;
    asm("{ .reg .u64 t; cvta.to.shared.u64 t, %1; cvt.u32.u64 %0, t; }"
        : "=r"(a) : "l"(p));
    return a;
}
__device__ __forceinline__ void split2(float a, float b, uint32_t& hi, uint32_t& lo) {
    uint32_t h;
    asm("cvt.rn.bf16x2.f32 %0, %1, %2;" : "=r"(h) : "f"(b), "f"(a));
    float ha = __uint_as_float(h << 16);
    float hb = __uint_as_float(h & 0xffff0000u);
    asm("cvt.rn.bf16x2.f32 %0, %1, %2;" : "=r"(lo) : "f"(b - hb), "f"(a - ha));
    hi = h;
}
__device__ __forceinline__ void split1(float x, unsigned short& hu, unsigned short& lu) {
    __nv_bfloat16 hb = __float2bfloat16(x);
    hu = *reinterpret_cast<unsigned short*>(&hb);
    float hf = __uint_as_float((uint32_t)hu << 16);
    __nv_bfloat16 lb = __float2bfloat16(x - hf);
    lu = *reinterpret_cast<unsigned short*>(&lb);
}
__device__ __forceinline__ void ldsm4(uint32_t addr, uint32_t& r0, uint32_t& r1,
                                      uint32_t& r2, uint32_t& r3) {
    asm volatile("ldmatrix.sync.aligned.m8n8.x4.shared.b16 {%0,%1,%2,%3}, [%4];"
                 : "=r"(r0), "=r"(r1), "=r"(r2), "=r"(r3) : "r"(addr));
}
__device__ __forceinline__ void mma16816(float* d, const uint32_t* a,
                                         uint32_t b0, uint32_t b1) {
    asm volatile("mma.sync.aligned.m16n8k16.row.col.f32.bf16.bf16.f32 "
                 "{%0,%1,%2,%3}, {%4,%5,%6,%7}, {%8,%9}, {%0,%1,%2,%3};"
                 : "+f"(d[0]), "+f"(d[1]), "+f"(d[2]), "+f"(d[3])
                 : "r"(a[0]), "r"(a[1]), "r"(a[2]), "r"(a[3]), "r"(b0), "r"(b1));
}
__device__ __forceinline__ void cpa16(uint32_t s, const void* g) {
    asm volatile("cp.async.cg.shared.global [%0], [%1], 16;" :: "r"(s), "l"(g));
}
#define CP_COMMIT() asm volatile("cp.async.commit_group;")
#define CP_WAIT0()  asm volatile("cp.async.wait_group 0;" ::: "memory")

// swizzled offsets (bank-conflict-free for ldmatrix, see analysis)
__device__ __forceinline__ uint32_t aoff(int row, int kb) {
    return (uint32_t)row * 512u + (uint32_t)(kb ^ ((row & 7) << 4));
}
__device__ __forceinline__ uint32_t boff(int n, int kb) {
    return (uint32_t)n * 64u + (uint32_t)(kb ^ (((n >> 1) & 3) << 4));
}

// ---------------- setup kernels ----------------
__global__ void prep_w01(const float* __restrict__ W0, const float* __restrict__ W1) {
    int idx = blockIdx.x * blockDim.x + threadIdx.x;   // 131072
    int layer = idx >> 16;
    int rem = idx & 65535;
    int k = rem >> 8, n = rem & 255;
    const float* W = layer ? W1 : W0;
    unsigned short hu, lu;
    split1(W[k * 256 + n], hu, lu);
    int c = k >> 5, kk = k & 31;
    uint32_t bp = (uint32_t)c * 16384u + boff(n, kk * 2);
    (layer ? gB1h : gB0h)[bp >> 1] = hu;
    (layer ? gB1l : gB0l)[bp >> 1] = lu;
}

__global__ void prep_wf(const float* __restrict__ W2, const float* __restrict__ Wqk,
                        const float* __restrict__ Wk) {
    int idx = blockIdx.x * blockDim.x + threadIdx.x;   // 32768
    int k = idx >> 7, n = idx & 127;
    float v;
    if (n < 32) {
        float s = 0.f;
        for (int c = 0; c < 64; c++) s += W2[k * 64 + c] * Wqk[c * 32 + n];
        v = s;
    } else if (n < 96) {
        v = W2[k * 64 + (n - 32)];
    } else {
        float s = 0.f;
        for (int c = 0; c < 64; c++) s += W2[k * 64 + c] * Wk[c * 32 + (n - 96)];
        v = s;
    }
    unsigned short hu, lu;
    split1(v, hu, lu);
    int c = k >> 5, kk = k & 31;
    uint32_t bp = (uint32_t)c * 8192u + boff(n, kk * 2);
    gBfh[bp >> 1] = hu;
    gBfl[bp >> 1] = lu;
}

__global__ void zero_out_kernel(float* __restrict__ out, int n) {
    int i = blockIdx.x * blockDim.x + threadIdx.x;
    if (i < n) out[i] = 0.f;
}

// ---------------- GEMM pieces ----------------
// one Kc=32 chunk of D[128,NF*8-per-warp] += (Ah+Al) @ (Bh+Bl), 3 passes
template<int NF>
__device__ __forceinline__ void compute_chunk(uint32_t SB, uint32_t bbase, int lo_off,
                                              float (*d)[4], int m0, int n0,
                                              int lane, int cbase) {
    const int lr = lane & 15;
    const int lh = (lane >> 4) * 16;
#pragma unroll
    for (int ks = 0; ks < 2; ks++) {
        const int kbA = cbase + ks * 32 + lh;
        uint32_t ah[2][4], al[2][4];
#pragma unroll
        for (int i = 0; i < 2; i++) {
            int row = m0 + 16 * i + lr;
            ldsm4(SB + OFF_AH + aoff(row, kbA), ah[i][0], ah[i][1], ah[i][2], ah[i][3]);
            ldsm4(SB + OFF_AL + aoff(row, kbA), al[i][0], al[i][1], al[i][2], al[i][3]);
        }
        const int kbB = ks * 32 + lh;
        uint32_t b[NF][2];
#pragma unroll
        for (int jj = 0; jj < NF / 2; jj++) {
            int n = n0 + jj * 16 + lr;
            uint32_t r0, r1, r2, r3;
            ldsm4(bbase + boff(n, kbB), r0, r1, r2, r3);
            b[jj * 2][0] = r0; b[jj * 2][1] = r2;
            b[jj * 2 + 1][0] = r1; b[jj * 2 + 1][1] = r3;
        }
#pragma unroll
        for (int i = 0; i < 2; i++)
#pragma unroll
            for (int j = 0; j < NF; j++) mma16816(d[i * NF + j], ah[i], b[j][0], b[j][1]);
#pragma unroll
        for (int i = 0; i < 2; i++)
#pragma unroll
            for (int j = 0; j < NF; j++) mma16816(d[i * NF + j], al[i], b[j][0], b[j][1]);
#pragma unroll
        for (int jj = 0; jj < NF / 2; jj++) {
            int n = n0 + jj * 16 + lr;
            uint32_t r0, r1, r2, r3;
            ldsm4(bbase + lo_off + boff(n, kbB), r0, r1, r2, r3);
            b[jj * 2][0] = r0; b[jj * 2][1] = r2;
            b[jj * 2 + 1][0] = r1; b[jj * 2 + 1][1] = r3;
        }
#pragma unroll
        for (int i = 0; i < 2; i++)
#pragma unroll
            for (int j = 0; j < NF; j++) mma16816(d[i * NF + j], ah[i], b[j][0], b[j][1]);
    }
}

// full layer: D = (A) @ B^T, K=256 in 8 chunks, cp.async double-buffered
template<int NF>
__device__ void run_layer(uint32_t SB, const uint4* __restrict__ gH,
                          const uint4* __restrict__ gL, int Nrows, bool active,
                          float (*d)[4], int m0, int n0, int lane, int tid) {
    const int nu4 = Nrows * 4;                  // uint4 per split per chunk
    const int lo_off = nu4 * 16;
    const uint32_t bb0 = SB + OFF_B0, bb1 = SB + OFF_B1;
    for (int i = tid; i < nu4; i += NTHREADS) cpa16(bb0 + i * 16, gH + i);
    for (int i = tid; i < nu4; i += NTHREADS) cpa16(bb0 + lo_off + i * 16, gL + i);
    CP_COMMIT();
    for (int c = 0; c < 8; c++) {
        CP_WAIT0();
        __syncthreads();
        if (c < 7) {
            const uint4* sh = gH + (c + 1) * nu4;
            const uint4* sl = gL + (c + 1) * nu4;
            uint32_t dst = ((c + 1) & 1) ? bb1 : bb0;
            for (int i = tid; i < nu4; i += NTHREADS) cpa16(dst + i * 16, sh + i);
            for (int i = tid; i < nu4; i += NTHREADS) cpa16(dst + lo_off + i * 16, sl + i);
            CP_COMMIT();
        }
        if (active)
            compute_chunk<NF>(SB, (c & 1) ? bb1 : bb0, lo_off, d, m0, n0, lane, c * 64);
    }
    __syncthreads();   // all warps done reading A/B before caller overwrites
}

// relu + split -> store as next layer's A (hi/lo, swizzled)
__device__ __forceinline__ void epi_hidden(char* smc, float (*d)[4], int m0, int n0, int lane) {
#pragma unroll
    for (int i = 0; i < 2; i++)
#pragma unroll
        for (int j = 0; j < 8; j++) {
            float* dd = d[i * 8 + j];
            int n = n0 + j * 8 + 2 * (lane & 3);
            int kb = n * 2;
            int r0 = m0 + 16 * i + (lane >> 2);
            uint32_t hi, lo;
            split2(fmaxf(dd[0], 0.f), fmaxf(dd[1], 0.f), hi, lo);
            *(uint32_t*)(smc + OFF_AH + aoff(r0, kb)) = hi;
            *(uint32_t*)(smc + OFF_AL + aoff(r0, kb)) = lo;
            split2(fmaxf(dd[2], 0.f), fmaxf(dd[3], 0.f), hi, lo);
            *(uint32_t*)(smc + OFF_AH + aoff(r0 + 8, kb)) = hi;
            *(uint32_t*)(smc + OFF_AL + aoff(r0 + 8, kb)) = lo;
        }
}

// load X[128,256] fp32, split, store to A hi/lo
__device__ __forceinline__ void stage_X(char* smc, const float* __restrict__ Xg,
                                        int e0, int tid) {
    int r = tid >> 2, qq = tid & 3;
    const float4* xr = (const float4*)(Xg + (size_t)(e0 + r) * 256) + qq * 16;
#pragma unroll
    for (int j = 0; j < 16; j++) {
        float4 v = xr[j];
        uint32_t h0, l0, h1, l1;
        split2(v.x, v.y, h0, l0);
        split2(v.z, v.w, h1, l1);
        int kb = (qq * 64 + j * 4) * 2;
        uint32_t off = aoff(r, kb);
        *(uint2*)(smc + OFF_AH + off) = make_uint2(h0, h1);
        *(uint2*)(smc + OFF_AL + off) = make_uint2(l0, l1);
    }
}

// ---------------- main fused kernel ----------------
__global__ void __launch_bounds__(NTHREADS, 1)
gnn_main(const float* __restrict__ src, const float* __restrict__ nbr,
         const float* __restrict__ ppr, const int* __restrict__ pidx,
         float* __restrict__ out) {
    extern __shared__ char smraw[];
    char* smc = (char*)(((uintptr_t)smraw + 1023) & ~(uintptr_t)1023);
    const uint32_t SB = smem_u32(smc);
    const int tid = threadIdx.x;
    const int lane = tid & 31;
    const int w = tid >> 5, wm = w >> 2, wn = w & 3;
    const int m0 = wm * 32, n0h = wn * 64, n0f = wn * 32;
    const int e0 = blockIdx.x * TILE;

    float* qsm  = (float*)(smc + OFF_Q);
    float* ksm  = (float*)(smc + OFF_KSM);
    float* wsm  = (float*)(smc + OFF_WSM);
    float* ewsm = (float*)(smc + OFF_EW);
    int*   gid  = (int*)(smc + OFF_GID);

#pragma unroll 1
    for (int path = 0; path < 2; path++) {
        stage_X(smc, path ? nbr : src, e0, tid);
        __syncthreads();
        {
            float d[16][4];
#pragma unroll
            for (int i = 0; i < 16; i++) { d[i][0] = d[i][1] = d[i][2] = d[i][3] = 0.f; }
            run_layer<8>(SB, (const uint4*)gB0h, (const uint4*)gB0l, 256, true,
                         d, m0, n0h, lane, tid);
            epi_hidden(smc, d, m0, n0h, lane);
            __syncthreads();
#pragma unroll
            for (int i = 0; i < 16; i++) { d[i][0] = d[i][1] = d[i][2] = d[i][3] = 0.f; }
            run_layer<8>(SB, (const uint4*)gB1h, (const uint4*)gB1l, 256, true,
                         d, m0, n0h, lane, tid);
            epi_hidden(smc, d, m0, n0h, lane);
            __syncthreads();
        }
        {
            float df[8][4];
#pragma unroll
            for (int i = 0; i < 8; i++) { df[i][0] = df[i][1] = df[i][2] = df[i][3] = 0.f; }
            bool act = (path == 0) ? (wn == 0) : (wn >= 1);
            run_layer<4>(SB, (const uint4*)gBfh, (const uint4*)gBfl, 128, act,
                         df, m0, n0f, lane, tid);
            if (path == 0) {
                if (wn == 0) {
#pragma unroll
                    for (int i = 0; i < 2; i++)
#pragma unroll
                        for (int j = 0; j < 4; j++) {
                            int n = j * 8 + 2 * (lane & 3);
                            int m = m0 + 16 * i + (lane >> 2);
                            float* dd = df[i * 4 + j];
                            qsm[m * 33 + n]           = dd[0];
                            qsm[m * 33 + n + 1]       = dd[1];
                            qsm[(m + 8) * 33 + n]     = dd[2];
                            qsm[(m + 8) * 33 + n + 1] = dd[3];
                        }
                }
                __syncthreads();
            } else {
                if (wn == 3) {    // k vector: global cols 96..127
#pragma unroll
                    for (int i = 0; i < 2; i++)
#pragma unroll
                        for (int j = 0; j < 4; j++) {
                            int h = j * 8 + 2 * (lane & 3);
                            int m = m0 + 16 * i + (lane >> 2);
                            float* dd = df[i * 4 + j];
                            ksm[m * 33 + h]           = dd[0];
                            ksm[m * 33 + h + 1]       = dd[1];
                            ksm[(m + 8) * 33 + h]     = dd[2];
                            ksm[(m + 8) * 33 + h + 1] = dd[3];
                        }
                }
                __syncthreads();
                if (tid < TILE) {
                    float s = 0.f;
#pragma unroll
                    for (int h = 0; h < HSZ; h++) s += qsm[tid * 33 + h] * ksm[tid * 33 + h];
                    ewsm[tid] = ppr[e0 + tid] / (1.f + expf(-s));
                    gid[tid]  = pidx[e0 + tid];
                }
                __syncthreads();
                if (wn == 1 || wn == 2) {   // x_n: global cols 32..95
#pragma unroll
                    for (int i = 0; i < 2; i++)
#pragma unroll
                        for (int j = 0; j < 4; j++) {
                            int cc = (wn - 1) * 32 + j * 8 + 2 * (lane & 3);
                            int m = m0 + 16 * i + (lane >> 2);
                            float* dd = df[i * 4 + j];
                            wsm[m * 65 + cc]           = dd[0];
                            wsm[m * 65 + cc + 1]       = dd[1];
                            wsm[(m + 8) * 65 + cc]     = dd[2];
                            wsm[(m + 8) * 65 + cc + 1] = dd[3];
                        }
                }
                __syncthreads();
                if (tid < 256) {   // RLE segmented atomics (ppr_idx sorted)
                    const int col = tid & 63;
                    const int base = (tid >> 6) * 32;
                    float acc = 0.f;
                    int prev = gid[base];
#pragma unroll
                    for (int i = 0; i < 32; i++) {
                        int g = gid[base + i];
                        if (g != prev) {
                            atomicAdd(out + (size_t)prev * NCLS + col, acc);
                            acc = 0.f;
                            prev = g;
                        }
                        acc += wsm[(base + i) * 65 + col] * ewsm[base + i];
                    }
                    atomicAdd(out + (size_t)prev * NCLS + col, acc);
                }
            }
        }
    }
}

// ---------------- launch ----------------
extern "C" void kernel_launch(void* const* d_in, const int* in_sizes, int n_in,
                              void* d_out, int out_size) {
    const float* src  = (const float*)d_in[0];
    const float* nbr  = (const float*)d_in[1];
    const float* ppr  = (const float*)d_in[2];
    const int*   pidx = (const int*)  d_in[3];
    // d_in[4] = neighbor_idx (unused by reference)
    const float* W0   = (const float*)d_in[5];
    const float* W1   = (const float*)d_in[6];
    const float* W2   = (const float*)d_in[7];
    const float* Wqk  = (const float*)d_in[8];
    const float* Wk   = (const float*)d_in[9];
    float* out = (float*)d_out;

    cudaFuncSetAttribute(gnn_main, cudaFuncAttributeMaxDynamicSharedMemorySize,
                         (int)SMEM_REQ);

    prep_w01<<<512, 256>>>(W0, W1);
    prep_wf<<<128, 256>>>(W2, Wqk, Wk);
    zero_out_kernel<<<(out_size + 255) / 256, 256>>>(out, out_size);
    gnn_main<<<NBLK, NTHREADS, SMEM_REQ>>>(src, nbr, ppr, pidx, out);
}

// round 9
// speedup vs baseline: 2.3935x; 1.0796x over previous
#include <cuda_runtime.h>
#include <cuda_bf16.h>
#include <math.h>
#include <stdint.h>

// ---------------- problem constants ----------------
#define E_TOT   400000
#define TILE    128
#define NBLK    (E_TOT / TILE)   // 3125
#define NCLS    64
#define HSZ     32
#define NTHREADS 512

// ---------------- smem byte offsets (from 1024-aligned base) -------------
#define OFF_AH   0u         // A hi  : 128 rows x 512B
#define OFF_AL   65536u     // A lo
#define OFF_B0   131072u    // B buf0: 32KB
#define OFF_B1   163840u    // B buf1: 32KB
#define OFF_Q    196608u    // q f32 [128][33]
#define OFF_EW   213504u    // ew f32 [128]
#define OFF_GID  214016u    // gid int [128]
#define OFF_KSM  131072u    // k f32 [128][33]  (alias over B0, post-GEMM)
#define OFF_WSM  148480u    // x_n f32 [128][65] (alias, post-GEMM)
#define SMEM_REQ (214528u + 1024u)

// ---------------- pre-split, pre-swizzled weights in global --------------
// per chunk (Kc=32): row n at byte n*64 + ((kk*2) ^ (((n>>1)&3)<<4))
__device__ unsigned short gB0h[65536], gB0l[65536];   // layer0, N=256, 8 chunks x 16KB
__device__ unsigned short gB1h[65536], gB1l[65536];   // layer1
__device__ unsigned short gBqh[8192],  gBql[8192];    // q image: N=32 (W2@Wqk), 8 x 2KB
__device__ unsigned short gBnh[24576], gBnl[24576];   // nbr final: N=96 [W2 | W2@Wk], 8 x 6KB

// ---------------- small helpers ----------------
__device__ __forceinline__ uint32_t smem_u32(const void* p) {
    uint32_t a;
    asm("{ .reg .u64 t; cvta.to.shared.u64 t, %1; cvt.u32.u64 %0, t; }"
        : "=r"(a) : "l"(p));
    return a;
}
__device__ __forceinline__ void split2(float a, float b, uint32_t& hi, uint32_t& lo) {
    uint32_t h;
    asm("cvt.rn.bf16x2.f32 %0, %1, %2;" : "=r"(h) : "f"(b), "f"(a));
    float ha = __uint_as_float(h << 16);
    float hb = __uint_as_float(h & 0xffff0000u);
    asm("cvt.rn.bf16x2.f32 %0, %1, %2;" : "=r"(lo) : "f"(b - hb), "f"(a - ha));
    hi = h;
}
__device__ __forceinline__ void split1(float x, unsigned short& hu, unsigned short& lu) {
    __nv_bfloat16 hb = __float2bfloat16(x);
    hu = *reinterpret_cast<unsigned short*>(&hb);
    float hf = __uint_as_float((uint32_t)hu << 16);
    __nv_bfloat16 lb = __float2bfloat16(x - hf);
    lu = *reinterpret_cast<unsigned short*>(&lb);
}
__device__ __forceinline__ void ldsm4(uint32_t addr, uint32_t& r0, uint32_t& r1,
                                      uint32_t& r2, uint32_t& r3) {
    asm volatile("ldmatrix.sync.aligned.m8n8.x4.shared.b16 {%0,%1,%2,%3}, [%4];"
                 : "=r"(r0), "=r"(r1), "=r"(r2), "=r"(r3) : "r"(addr));
}
__device__ __forceinline__ void mma16816(float* d, const uint32_t* a,
                                         uint32_t b0, uint32_t b1) {
    asm volatile("mma.sync.aligned.m16n8k16.row.col.f32.bf16.bf16.f32 "
                 "{%0,%1,%2,%3}, {%4,%5,%6,%7}, {%8,%9}, {%0,%1,%2,%3};"
                 : "+f"(d[0]), "+f"(d[1]), "+f"(d[2]), "+f"(d[3])
                 : "r"(a[0]), "r"(a[1]), "r"(a[2]), "r"(a[3]), "r"(b0), "r"(b1));
}
__device__ __forceinline__ void cpa16(uint32_t s, const void* g) {
    asm volatile("cp.async.cg.shared.global [%0], [%1], 16;" :: "r"(s), "l"(g));
}
#define CP_COMMIT() asm volatile("cp.async.commit_group;")
#define CP_WAIT0()  asm volatile("cp.async.wait_group 0;" ::: "memory")

// swizzled offsets (conflict-free for ldmatrix)
__device__ __forceinline__ uint32_t aoff(int row, int kb) {
    return (uint32_t)row * 512u + (uint32_t)(kb ^ ((row & 7) << 4));
}
__device__ __forceinline__ uint32_t boff(int n, int kb) {
    return (uint32_t)n * 64u + (uint32_t)(kb ^ (((n >> 1) & 3) << 4));
}

// ---------------- setup kernels ----------------
__global__ void prep_w01(const float* __restrict__ W0, const float* __restrict__ W1) {
    int idx = blockIdx.x * blockDim.x + threadIdx.x;   // 131072
    int layer = idx >> 16;
    int rem = idx & 65535;
    int k = rem >> 8, n = rem & 255;
    const float* W = layer ? W1 : W0;
    unsigned short hu, lu;
    split1(W[k * 256 + n], hu, lu);
    int c = k >> 5, kk = k & 31;
    uint32_t bp = (uint32_t)c * 16384u + boff(n, kk * 2);
    (layer ? gB1h : gB0h)[bp >> 1] = hu;
    (layer ? gB1l : gB0l)[bp >> 1] = lu;
}

__global__ void prep_wf(const float* __restrict__ W2, const float* __restrict__ Wqk,
                        const float* __restrict__ Wk) {
    int idx = blockIdx.x * blockDim.x + threadIdx.x;   // 32768
    int k = idx >> 7, n = idx & 127;
    int c = k >> 5, kk = k & 31;
    unsigned short hu, lu;
    if (n < 32) {   // q image col n
        float s = 0.f;
        for (int cc = 0; cc < 64; cc++) s += W2[k * 64 + cc] * Wqk[cc * 32 + n];
        split1(s, hu, lu);
        uint32_t bp = (uint32_t)c * 2048u + boff(n, kk * 2);
        gBqh[bp >> 1] = hu; gBql[bp >> 1] = lu;
    } else {        // nbr-final image col m (0..95)
        int m = n - 32;
        float v;
        if (m < 64) v = W2[k * 64 + m];
        else {
            float s = 0.f;
            for (int cc = 0; cc < 64; cc++) s += W2[k * 64 + cc] * Wk[cc * 32 + (m - 64)];
            v = s;
        }
        split1(v, hu, lu);
        uint32_t bp = (uint32_t)c * 6144u + boff(m, kk * 2);
        gBnh[bp >> 1] = hu; gBnl[bp >> 1] = lu;
    }
}

__global__ void zero_out_kernel(float* __restrict__ out, int n) {
    int i = blockIdx.x * blockDim.x + threadIdx.x;
    if (i < n) out[i] = 0.f;
}

// ---------------- GEMM pieces ----------------
// one Kc=32 chunk of D += (Ah+Al)@(Bh+Bl), 3 passes
template<int NF>
__device__ __forceinline__ void compute_chunk(uint32_t SB, uint32_t bbase, int lo_off,
                                              float (*d)[4], int m0, int n0,
                                              int lane, int cbase) {
    const int lr = lane & 15;
    const int lh = (lane >> 4) * 16;
#pragma unroll
    for (int ks = 0; ks < 2; ks++) {
        const int kbA = cbase + ks * 32 + lh;
        uint32_t ah[2][4], al[2][4];
#pragma unroll
        for (int i = 0; i < 2; i++) {
            int row = m0 + 16 * i + lr;
            ldsm4(SB + OFF_AH + aoff(row, kbA), ah[i][0], ah[i][1], ah[i][2], ah[i][3]);
            ldsm4(SB + OFF_AL + aoff(row, kbA), al[i][0], al[i][1], al[i][2], al[i][3]);
        }
        const int kbB = ks * 32 + lh;
        uint32_t b[NF][2];
#pragma unroll
        for (int jj = 0; jj < NF / 2; jj++) {
            int n = n0 + jj * 16 + lr;
            uint32_t r0, r1, r2, r3;
            ldsm4(bbase + boff(n, kbB), r0, r1, r2, r3);
            b[jj * 2][0] = r0; b[jj * 2][1] = r2;
            b[jj * 2 + 1][0] = r1; b[jj * 2 + 1][1] = r3;
        }
#pragma unroll
        for (int i = 0; i < 2; i++)
#pragma unroll
            for (int j = 0; j < NF; j++) mma16816(d[i * NF + j], ah[i], b[j][0], b[j][1]);
#pragma unroll
        for (int i = 0; i < 2; i++)
#pragma unroll
            for (int j = 0; j < NF; j++) mma16816(d[i * NF + j], al[i], b[j][0], b[j][1]);
#pragma unroll
        for (int jj = 0; jj < NF / 2; jj++) {
            int n = n0 + jj * 16 + lr;
            uint32_t r0, r1, r2, r3;
            ldsm4(bbase + lo_off + boff(n, kbB), r0, r1, r2, r3);
            b[jj * 2][0] = r0; b[jj * 2][1] = r2;
            b[jj * 2 + 1][0] = r1; b[jj * 2 + 1][1] = r3;
        }
#pragma unroll
        for (int i = 0; i < 2; i++)
#pragma unroll
            for (int j = 0; j < NF; j++) mma16816(d[i * NF + j], ah[i], b[j][0], b[j][1]);
    }
}

// full layer: K=256 in 8 chunks, cp.async double buffered.
// pre: chunk0 already in buf(pb).  At c==7 prefetches nxc uint4 (hi) + nxc (lo)
// of the NEXT image into buf(pb), chaining parity (next layer uses same pb).
template<int NF>
__device__ void run_layer(uint32_t SB, const uint4* __restrict__ gH,
                          const uint4* __restrict__ gL, int nu4,
                          bool pre, int pb, bool active,
                          const uint4* __restrict__ nxH, const uint4* __restrict__ nxL,
                          int nxc, float (*d)[4], int m0, int n0, int lane, int tid) {
    const int lo_off = nu4 * 16;
    const uint32_t buf0 = SB + OFF_B0, buf1 = SB + OFF_B1;
    if (!pre) {
        uint32_t dst = pb ? buf1 : buf0;
        for (int i = tid; i < nu4; i += NTHREADS) {
            cpa16(dst + i * 16, gH + i);
            cpa16(dst + lo_off + i * 16, gL + i);
        }
        CP_COMMIT();
    }
    for (int c = 0; c < 8; c++) {
        CP_WAIT0();
        __syncthreads();
        if (c < 7) {
            uint32_t dst = (((c + 1 + pb) & 1) ? buf1 : buf0);
            const uint4* sh = gH + (c + 1) * nu4;
            const uint4* sl = gL + (c + 1) * nu4;
            for (int i = tid; i < nu4; i += NTHREADS) {
                cpa16(dst + i * 16, sh + i);
                cpa16(dst + lo_off + i * 16, sl + i);
            }
            CP_COMMIT();
        } else if (nxc) {
            uint32_t dst = pb ? buf1 : buf0;
            for (int i = tid; i < nxc; i += NTHREADS) {
                cpa16(dst + i * 16, nxH + i);
                cpa16(dst + nxc * 16 + i * 16, nxL + i);
            }
            CP_COMMIT();
        }
        if (active)
            compute_chunk<NF>(SB, (((c + pb) & 1) ? buf1 : buf0), lo_off,
                              d, m0, n0, lane, c * 64);
    }
    __syncthreads();   // compute done before caller overwrites A / buffers
}

// relu + split -> next layer's A (hi/lo, swizzled)
__device__ __forceinline__ void epi_hidden(char* smc, float (*d)[4], int m0, int n0, int lane) {
#pragma unroll
    for (int i = 0; i < 2; i++)
#pragma unroll
        for (int j = 0; j < 8; j++) {
            float* dd = d[i * 8 + j];
            int n = n0 + j * 8 + 2 * (lane & 3);
            int kb = n * 2;
            int r0 = m0 + 16 * i + (lane >> 2);
            uint32_t hi, lo;
            split2(fmaxf(dd[0], 0.f), fmaxf(dd[1], 0.f), hi, lo);
            *(uint32_t*)(smc + OFF_AH + aoff(r0, kb)) = hi;
            *(uint32_t*)(smc + OFF_AL + aoff(r0, kb)) = lo;
            split2(fmaxf(dd[2], 0.f), fmaxf(dd[3], 0.f), hi, lo);
            *(uint32_t*)(smc + OFF_AH + aoff(r0 + 8, kb)) = hi;
            *(uint32_t*)(smc + OFF_AL + aoff(r0 + 8, kb)) = lo;
        }
}

// load X[128,256] fp32, split, store to A hi/lo
__device__ __forceinline__ void stage_X(char* smc, const float* __restrict__ Xg,
                                        int e0, int tid) {
    int r = tid >> 2, qq = tid & 3;
    const float4* xr = (const float4*)(Xg + (size_t)(e0 + r) * 256) + qq * 16;
#pragma unroll
    for (int j = 0; j < 16; j++) {
        float4 v = xr[j];
        uint32_t h0, l0, h1, l1;
        split2(v.x, v.y, h0, l0);
        split2(v.z, v.w, h1, l1);
        int kb = (qq * 64 + j * 4) * 2;
        uint32_t off = aoff(r, kb);
        *(uint2*)(smc + OFF_AH + off) = make_uint2(h0, h1);
        *(uint2*)(smc + OFF_AL + off) = make_uint2(l0, l1);
    }
}

// ---------------- main fused kernel ----------------
__global__ void __launch_bounds__(NTHREADS, 1)
gnn_main(const float* __restrict__ src, const float* __restrict__ nbr,
         const float* __restrict__ ppr, const int* __restrict__ pidx,
         float* __restrict__ out) {
    extern __shared__ char smraw[];
    char* smc = (char*)(((uintptr_t)smraw + 1023) & ~(uintptr_t)1023);
    const uint32_t SB = smem_u32(smc);
    const int tid = threadIdx.x;
    const int lane = tid & 31;
    const int w = tid >> 5, wm = w >> 2, wn = w & 3;
    const int m0 = wm * 32, n0h = wn * 64;
    const int e0 = blockIdx.x * TILE;

    float* qsm  = (float*)(smc + OFF_Q);
    float* ksm  = (float*)(smc + OFF_KSM);
    float* wsm  = (float*)(smc + OFF_WSM);
    float* ewsm = (float*)(smc + OFF_EW);
    int*   gid  = (int*)(smc + OFF_GID);

    float d[16][4];

    // =========== PATH 0 (source) ===========
    stage_X(smc, src, e0, tid);
#pragma unroll
    for (int i = 0; i < 16; i++) { d[i][0] = d[i][1] = d[i][2] = d[i][3] = 0.f; }
    run_layer<8>(SB, (const uint4*)gB0h, (const uint4*)gB0l, 1024, false, 0, true,
                 (const uint4*)gB1h, (const uint4*)gB1l, 1024, d, m0, n0h, lane, tid);
    epi_hidden(smc, d, m0, n0h, lane);
#pragma unroll
    for (int i = 0; i < 16; i++) { d[i][0] = d[i][1] = d[i][2] = d[i][3] = 0.f; }
    run_layer<8>(SB, (const uint4*)gB1h, (const uint4*)gB1l, 1024, true, 0, true,
                 (const uint4*)gBqh, (const uint4*)gBql, 1024, d, m0, n0h, lane, tid);
    epi_hidden(smc, d, m0, n0h, lane);

    // =========== q final: K-split across warp columns ===========
    CP_WAIT0();            // Bq image (32KB burst) landed in buf0
    __syncthreads();       // epi writes visible
    {   // prefetch path1 layer0 chunk0 into buf1 (overlaps q compute + stage_X)
        uint32_t dst = SB + OFF_B1;
        for (int i = tid; i < 1024; i += NTHREADS) {
            cpa16(dst + i * 16, (const uint4*)gB0h + i);
            cpa16(dst + 16384 + i * 16, (const uint4*)gB0l + i);
        }
        CP_COMMIT();
    }
    {
        float dq[8][4];
#pragma unroll
        for (int i = 0; i < 8; i++) { dq[i][0] = dq[i][1] = dq[i][2] = dq[i][3] = 0.f; }
        uint32_t bq = SB + OFF_B0;
        compute_chunk<4>(SB, bq + (2 * wn) * 2048, 16384, dq, m0, 0, lane, (2 * wn) * 64);
        compute_chunk<4>(SB, bq + (2 * wn + 1) * 2048, 16384, dq, m0, 0, lane, (2 * wn + 1) * 64);
        __syncthreads();   // all warps done reading A -> AH reusable as partials
        float* part = (float*)(smc + OFF_AH) + wn * 4096;
#pragma unroll
        for (int i = 0; i < 2; i++)
#pragma unroll
            for (int j = 0; j < 4; j++) {
                int n = j * 8 + 2 * (lane & 3);
                int m = m0 + 16 * i + (lane >> 2);
                float* dd = dq[i * 4 + j];
                part[m * 32 + n]           = dd[0];
                part[m * 32 + n + 1]       = dd[1];
                part[(m + 8) * 32 + n]     = dd[2];
                part[(m + 8) * 32 + n + 1] = dd[3];
            }
        __syncthreads();
        float* P = (float*)(smc + OFF_AH);
        for (int i = tid; i < 4096; i += NTHREADS) {
            int m = i >> 5, n = i & 31;
            qsm[m * 33 + n] = P[i] + P[4096 + i] + P[8192 + i] + P[12288 + i];
        }
        __syncthreads();   // reduce done before stage_X overwrites AH
    }

    // =========== PATH 1 (neighbor) ===========
    stage_X(smc, nbr, e0, tid);
#pragma unroll
    for (int i = 0; i < 16; i++) { d[i][0] = d[i][1] = d[i][2] = d[i][3] = 0.f; }
    run_layer<8>(SB, (const uint4*)gB0h, (const uint4*)gB0l, 1024, true, 1, true,
                 (const uint4*)gB1h, (const uint4*)gB1l, 1024, d, m0, n0h, lane, tid);
    epi_hidden(smc, d, m0, n0h, lane);
#pragma unroll
    for (int i = 0; i < 16; i++) { d[i][0] = d[i][1] = d[i][2] = d[i][3] = 0.f; }
    run_layer<8>(SB, (const uint4*)gB1h, (const uint4*)gB1l, 1024, true, 1, true,
                 (const uint4*)gBnh, (const uint4*)gBnl, 384, d, m0, n0h, lane, tid);
    epi_hidden(smc, d, m0, n0h, lane);

    {   // neighbor final: N=96 image [x_n(64) | k(32)], warps wn<3 active
        float df[8][4];
#pragma unroll
        for (int i = 0; i < 8; i++) { df[i][0] = df[i][1] = df[i][2] = df[i][3] = 0.f; }
        run_layer<4>(SB, (const uint4*)gBnh, (const uint4*)gBnl, 384, true, 1, (wn < 3),
                     (const uint4*)0, (const uint4*)0, 0, df, m0, wn * 32, lane, tid);
        if (wn == 2) {        // k -> ksm
#pragma unroll
            for (int i = 0; i < 2; i++)
#pragma unroll
                for (int j = 0; j < 4; j++) {
                    int h = j * 8 + 2 * (lane & 3);
                    int m = m0 + 16 * i + (lane >> 2);
                    float* dd = df[i * 4 + j];
                    ksm[m * 33 + h]           = dd[0];
                    ksm[m * 33 + h + 1]       = dd[1];
                    ksm[(m + 8) * 33 + h]     = dd[2];
                    ksm[(m + 8) * 33 + h + 1] = dd[3];
                }
        } else if (wn < 2) {  // x_n -> wsm
#pragma unroll
            for (int i = 0; i < 2; i++)
#pragma unroll
                for (int j = 0; j < 4; j++) {
                    int cc = wn * 32 + j * 8 + 2 * (lane & 3);
                    int m = m0 + 16 * i + (lane >> 2);
                    float* dd = df[i * 4 + j];
                    wsm[m * 65 + cc]           = dd[0];
                    wsm[m * 65 + cc + 1]       = dd[1];
                    wsm[(m + 8) * 65 + cc]     = dd[2];
                    wsm[(m + 8) * 65 + cc + 1] = dd[3];
                }
        }
        __syncthreads();
        if (tid < TILE) {     // attention scalar
            float s = 0.f;
#pragma unroll
            for (int h = 0; h < HSZ; h++) s += qsm[tid * 33 + h] * ksm[tid * 33 + h];
            ewsm[tid] = ppr[e0 + tid] / (1.f + expf(-s));
            gid[tid]  = pidx[e0 + tid];
        }
        __syncthreads();
        if (tid < 256) {      // RLE segmented atomics (ppr_idx sorted)
            const int col = tid & 63;
            const int base = (tid >> 6) * 32;
            float acc = 0.f;
            int prev = gid[base];
#pragma unroll
            for (int i = 0; i < 32; i++) {
                int g = gid[base + i];
                if (g != prev) {
                    atomicAdd(out + (size_t)prev * NCLS + col, acc);
                    acc = 0.f;
                    prev = g;
                }
                acc += wsm[(base + i) * 65 + col] * ewsm[base + i];
            }
            atomicAdd(out + (size_t)prev * NCLS + col, acc);
        }
    }
}

// ---------------- launch ----------------
extern "C" void kernel_launch(void* const* d_in, const int* in_sizes, int n_in,
                              void* d_out, int out_size) {
    const float* src  = (const float*)d_in[0];
    const float* nbr  = (const float*)d_in[1];
    const float* ppr  = (const float*)d_in[2];
    const int*   pidx = (const int*)  d_in[3];
    // d_in[4] = neighbor_idx (unused by reference)
    const float* W0   = (const float*)d_in[5];
    const float* W1   = (const float*)d_in[6];
    const float* W2   = (const float*)d_in[7];
    const float* Wqk  = (const float*)d_in[8];
    const float* Wk   = (const float*)d_in[9];
    float* out = (float*)d_out;

    cudaFuncSetAttribute(gnn_main, cudaFuncAttributeMaxDynamicSharedMemorySize,
                         (int)SMEM_REQ);

    prep_w01<<<512, 256>>>(W0, W1);
    prep_wf<<<128, 256>>>(W2, Wqk, Wk);
    zero_out_kernel<<<(out_size + 255) / 256, 256>>>(out, out_size);
    gnn_main<<<NBLK, NTHREADS, SMEM_REQ>>>(src, nbr, ppr, pidx, out);
}

// round 10
// speedup vs baseline: 2.6809x; 1.1201x over previous
#include <cuda_runtime.h>
#include <cuda_bf16.h>
#include <math.h>
#include <stdint.h>

// ---------------- problem constants ----------------
#define E_TOT   400000
#define TILE    64
#define NBLK    (E_TOT / TILE)   // 6250
#define NCLS    64
#define HSZ     32
#define NTHREADS 256

// ---------------- smem layout (from 1024-aligned base) ----------------
#define OFF_AH   0u          // A hi : 64 rows x 512B = 32KB
#define OFF_AL   32768u      // A lo : 32KB
#define OFF_B    65536u      // 4 groups x 2 bufs x 4KB = 32KB
#define OFF_Q    98304u      // q f32 [64][33] = 8448B
#define OFF_EW   106752u     // ew f32 [64]
#define OFF_GID  107008u     // gid int [64]
#define OFF_KSM  65536u      // k  f32 [64][33] (alias over B, post-GEMM)
#define OFF_WSM  74240u      // xn f32 [64][65] (alias over B, post-GEMM)
#define SMEM_REQ (107264u + 1024u)

// ---------------- pre-split, pre-swizzled weights ----------------
// Kc=16 chunks; within chunk, row n (32B): byte n*32 + ((kk*2)^(((n>>2)&1)<<4))
__device__ unsigned short gB0h[65536], gB0l[65536];   // layer0: 16 chunks x 8KB
__device__ unsigned short gB1h[65536], gB1l[65536];   // layer1
__device__ unsigned short gBqh[8192],  gBql[8192];    // q image N=32 (W2@Wqk): 16 x 1KB
__device__ unsigned short gBnh[24576], gBnl[24576];   // final N=96 [W2 | W2@Wk]: 16 x 3KB

// ---------------- helpers ----------------
__device__ __forceinline__ uint32_t smem_u32(const void* p) {
    uint32_t a;
    asm("{ .reg .u64 t; cvta.to.shared.u64 t, %1; cvt.u32.u64 %0, t; }"
        : "=r"(a) : "l"(p));
    return a;
}
__device__ __forceinline__ void split2(float a, float b, uint32_t& hi, uint32_t& lo) {
    uint32_t h;
    asm("cvt.rn.bf16x2.f32 %0, %1, %2;" : "=r"(h) : "f"(b), "f"(a));
    float ha = __uint_as_float(h << 16);
    float hb = __uint_as_float(h & 0xffff0000u);
    asm("cvt.rn.bf16x2.f32 %0, %1, %2;" : "=r"(lo) : "f"(b - hb), "f"(a - ha));
    hi = h;
}
__device__ __forceinline__ void split1(float x, unsigned short& hu, unsigned short& lu) {
    __nv_bfloat16 hb = __float2bfloat16(x);
    hu = *reinterpret_cast<unsigned short*>(&hb);
    float hf = __uint_as_float((uint32_t)hu << 16);
    __nv_bfloat16 lb = __float2bfloat16(x - hf);
    lu = *reinterpret_cast<unsigned short*>(&lb);
}
__device__ __forceinline__ void ldsm4(uint32_t addr, uint32_t& r0, uint32_t& r1,
                                      uint32_t& r2, uint32_t& r3) {
    asm volatile("ldmatrix.sync.aligned.m8n8.x4.shared.b16 {%0,%1,%2,%3}, [%4];"
                 : "=r"(r0), "=r"(r1), "=r"(r2), "=r"(r3) : "r"(addr));
}
__device__ __forceinline__ void mma16816(float* d, const uint32_t* a,
                                         uint32_t b0, uint32_t b1) {
    asm volatile("mma.sync.aligned.m16n8k16.row.col.f32.bf16.bf16.f32 "
                 "{%0,%1,%2,%3}, {%4,%5,%6,%7}, {%8,%9}, {%0,%1,%2,%3};"
                 : "+f"(d[0]), "+f"(d[1]), "+f"(d[2]), "+f"(d[3])
                 : "r"(a[0]), "r"(a[1]), "r"(a[2]), "r"(a[3]), "r"(b0), "r"(b1));
}
__device__ __forceinline__ void cpa16(uint32_t s, const void* g) {
    asm volatile("cp.async.cg.shared.global [%0], [%1], 16;" :: "r"(s), "l"(g));
}
#define CP_COMMIT() asm volatile("cp.async.commit_group;")
#define CP_WAIT1()  asm volatile("cp.async.wait_group 1;" ::: "memory")
#define BARG(id)    asm volatile("bar.sync %0, 64;" :: "r"(id) : "memory")

// A swizzle: row = 512B, conflict-free ldmatrix
__device__ __forceinline__ uint32_t aoff(int row, int kb) {
    return (uint32_t)row * 512u + (uint32_t)(kb ^ ((row & 7) << 4));
}
// B swizzle within slice/chunk: row = 32B
__device__ __forceinline__ uint32_t bxor(int r, int lh) {
    return (uint32_t)r * 32u + (uint32_t)(lh ^ (((r >> 2) & 1) << 4));
}

// ---------------- setup kernels ----------------
__global__ void prep_w01(const float* __restrict__ W0, const float* __restrict__ W1) {
    int idx = blockIdx.x * blockDim.x + threadIdx.x;   // 131072
    int layer = idx >> 16;
    int rem = idx & 65535;
    int k = rem >> 8, n = rem & 255;
    const float* W = layer ? W1 : W0;
    unsigned short hu, lu;
    split1(W[k * 256 + n], hu, lu);
    int c = k >> 4, kk = k & 15;
    uint32_t bp = (uint32_t)c * 8192u + bxor(n, kk * 2);
    (layer ? gB1h : gB0h)[bp >> 1] = hu;
    (layer ? gB1l : gB0l)[bp >> 1] = lu;
}

__global__ void prep_wf(const float* __restrict__ W2, const float* __restrict__ Wqk,
                        const float* __restrict__ Wk) {
    int idx = blockIdx.x * blockDim.x + threadIdx.x;   // 32768
    int k = idx >> 7, n = idx & 127;
    int c = k >> 4, kk = k & 15;
    unsigned short hu, lu;
    if (n < 32) {
        float s = 0.f;
        for (int cc = 0; cc < 64; cc++) s += W2[k * 64 + cc] * Wqk[cc * 32 + n];
        split1(s, hu, lu);
        uint32_t bp = (uint32_t)c * 1024u + bxor(n, kk * 2);
        gBqh[bp >> 1] = hu; gBql[bp >> 1] = lu;
    } else {
        int m = n - 32;
        float v;
        if (m < 64) v = W2[k * 64 + m];
        else {
            float s = 0.f;
            for (int cc = 0; cc < 64; cc++) s += W2[k * 64 + cc] * Wk[cc * 32 + (m - 64)];
            v = s;
        }
        split1(v, hu, lu);
        uint32_t bp = (uint32_t)c * 3072u + bxor(m, kk * 2);
        gBnh[bp >> 1] = hu; gBnl[bp >> 1] = lu;
    }
}

__global__ void zero_out_kernel(float* __restrict__ out, int n) {
    int i = blockIdx.x * blockDim.x + threadIdx.x;
    if (i < n) out[i] = 0.f;
}

// ---------------- GEMM pieces ----------------
// one Kc=16 chunk: D += (Ah+Al)@(Bh+Bl), 3 passes; buf = [hi 2KB | lo 2KB]
template<int NF>
__device__ __forceinline__ void compute_grp(uint32_t SB, uint32_t buf,
                                            float (*d)[4], int m0, int lane, int kbA0) {
    const int lr = lane & 15;
    const int lh = (lane >> 4) * 16;
    const int kbA = kbA0 + lh;
    uint32_t ah[2][4], al[2][4];
#pragma unroll
    for (int i = 0; i < 2; i++) {
        int row = m0 + 16 * i + lr;
        ldsm4(SB + OFF_AH + aoff(row, kbA), ah[i][0], ah[i][1], ah[i][2], ah[i][3]);
        ldsm4(SB + OFF_AL + aoff(row, kbA), al[i][0], al[i][1], al[i][2], al[i][3]);
    }
    uint32_t b[NF][2];
#pragma unroll
    for (int jj = 0; jj < NF / 2; jj++) {
        int r = jj * 16 + lr;
        uint32_t r0, r1, r2, r3;
        ldsm4(buf + bxor(r, lh), r0, r1, r2, r3);
        b[2 * jj][0] = r0; b[2 * jj][1] = r2;
        b[2 * jj + 1][0] = r1; b[2 * jj + 1][1] = r3;
    }
#pragma unroll
    for (int i = 0; i < 2; i++)
#pragma unroll
        for (int j = 0; j < NF; j++) mma16816(d[i * NF + j], ah[i], b[j][0], b[j][1]);
#pragma unroll
    for (int i = 0; i < 2; i++)
#pragma unroll
        for (int j = 0; j < NF; j++) mma16816(d[i * NF + j], al[i], b[j][0], b[j][1]);
#pragma unroll
    for (int jj = 0; jj < NF / 2; jj++) {
        int r = jj * 16 + lr;
        uint32_t r0, r1, r2, r3;
        ldsm4(buf + 2048u + bxor(r, lh), r0, r1, r2, r3);
        b[2 * jj][0] = r0; b[2 * jj][1] = r2;
        b[2 * jj + 1][0] = r1; b[2 * jj + 1][1] = r3;
    }
#pragma unroll
    for (int i = 0; i < 2; i++)
#pragma unroll
        for (int j = 0; j < NF; j++) mma16816(d[i * NF + j], ah[i], b[j][0], b[j][1]);
}

// group copies its own slice (hi+lo) + commit (1 group)
__device__ __forceinline__ void copy_slice(uint32_t dst, const char* srcH,
                                           const char* srcL, int nbytes, int lt) {
    for (int i = lt * 16; i < nbytes; i += 64 * 16) {
        cpa16(dst + i, srcH + i);
        cpa16(dst + 2048u + i, srcL + i);
    }
    CP_COMMIT();
}

// full layer: 16 chunks, group-private double buffer, named barriers.
// pre: chunks 0,1 already committed into buf0,buf1.
// At c=14/15 prefetches next image chunks 0,1 (or empty-commits).
template<int NF>
__device__ void run_layer_grp(uint32_t SB, uint32_t gb,
        const char* gH, const char* gL, int chunkB, int sliceOff, int sliceB,
        bool pre, const char* nxH, const char* nxL, int nxChunkB, int nxSliceOff,
        int nxSliceB, float (*d)[4], int m0, int lane, int lt, int barid) {
    if (!pre) {
        copy_slice(gb,         gH + sliceOff,          gL + sliceOff,          sliceB, lt);
        copy_slice(gb + 4096u, gH + chunkB + sliceOff, gL + chunkB + sliceOff, sliceB, lt);
    }
#pragma unroll 1
    for (int c = 0; c < 16; c++) {
        CP_WAIT1();
        BARG(barid);
        compute_grp<NF>(SB, gb + (c & 1) * 4096u, d, m0, lane, c * 32);
        BARG(barid);
        if (c < 14) {
            copy_slice(gb + (c & 1) * 4096u, gH + (c + 2) * chunkB + sliceOff,
                       gL + (c + 2) * chunkB + sliceOff, sliceB, lt);
        } else if (nxSliceB) {
            int cc = c - 14;
            copy_slice(gb + (cc & 1) * 4096u, nxH + cc * nxChunkB + nxSliceOff,
                       nxL + cc * nxChunkB + nxSliceOff, nxSliceB, lt);
        } else {
            CP_COMMIT();
        }
    }
}

// relu + split -> next layer's A
__device__ __forceinline__ void epi_hidden(char* smc, float (*d)[4], int m0, int n0, int lane) {
#pragma unroll
    for (int i = 0; i < 2; i++)
#pragma unroll
        for (int j = 0; j < 8; j++) {
            float* dd = d[i * 8 + j];
            int n = n0 + j * 8 + 2 * (lane & 3);
            int kb = n * 2;
            int r0 = m0 + 16 * i + (lane >> 2);
            uint32_t hi, lo;
            split2(fmaxf(dd[0], 0.f), fmaxf(dd[1], 0.f), hi, lo);
            *(uint32_t*)(smc + OFF_AH + aoff(r0, kb)) = hi;
            *(uint32_t*)(smc + OFF_AL + aoff(r0, kb)) = lo;
            split2(fmaxf(dd[2], 0.f), fmaxf(dd[3], 0.f), hi, lo);
            *(uint32_t*)(smc + OFF_AH + aoff(r0 + 8, kb)) = hi;
            *(uint32_t*)(smc + OFF_AL + aoff(r0 + 8, kb)) = lo;
        }
}

// load X[64,256] fp32, split, store to A hi/lo
__device__ __forceinline__ void stage_X(char* smc, const float* __restrict__ Xg,
                                        int e0, int tid) {
    int r = tid >> 2, qq = tid & 3;
    const float4* xr = (const float4*)(Xg + (size_t)(e0 + r) * 256) + qq * 16;
#pragma unroll
    for (int j = 0; j < 16; j++) {
        float4 v = xr[j];
        uint32_t h0, l0, h1, l1;
        split2(v.x, v.y, h0, l0);
        split2(v.z, v.w, h1, l1);
        int kb = (qq * 64 + j * 4) * 2;
        uint32_t off = aoff(r, kb);
        *(uint2*)(smc + OFF_AH + off) = make_uint2(h0, h1);
        *(uint2*)(smc + OFF_AL + off) = make_uint2(l0, l1);
    }
}

// ---------------- main fused kernel ----------------
__global__ void __launch_bounds__(NTHREADS, 2)
gnn_main(const float* __restrict__ src, const float* __restrict__ nbr,
         const float* __restrict__ ppr, const int* __restrict__ pidx,
         float* __restrict__ out) {
    extern __shared__ char smraw[];
    char* smc = (char*)(((uintptr_t)smraw + 1023) & ~(uintptr_t)1023);
    const uint32_t SB = smem_u32(smc);
    const int tid = threadIdx.x;
    const int lane = tid & 31;
    const int w = tid >> 5, wm = w >> 2, wn = w & 3;
    const int m0 = wm * 32, n0h = wn * 64;
    const int lt = wm * 32 + lane;        // thread index within wn-group (0..63)
    const int barid = wn + 1;
    const uint32_t gb = SB + OFF_B + (uint32_t)wn * 8192u;
    const int e0 = blockIdx.x * TILE;

    float* qsm  = (float*)(smc + OFF_Q);
    float* ksm  = (float*)(smc + OFF_KSM);
    float* wsm  = (float*)(smc + OFF_WSM);
    float* ewsm = (float*)(smc + OFF_EW);
    int*   gid  = (int*)(smc + OFF_GID);

    const char* B0h = (const char*)gB0h; const char* B0l = (const char*)gB0l;
    const char* B1h = (const char*)gB1h; const char* B1l = (const char*)gB1l;
    const char* Qh  = (const char*)gBqh; const char* Ql  = (const char*)gBql;
    const char* Nh  = (const char*)gBnh; const char* Nl  = (const char*)gBnl;

    float d[16][4];

    // =========== PATH 0 (source) ===========
    stage_X(smc, src, e0, tid);
    __syncthreads();
#pragma unroll
    for (int i = 0; i < 16; i++) { d[i][0] = d[i][1] = d[i][2] = d[i][3] = 0.f; }
    run_layer_grp<8>(SB, gb, B0h, B0l, 8192, wn * 2048, 2048, false,
                     B1h, B1l, 8192, wn * 2048, 2048, d, m0, lane, lt, barid);
    __syncthreads();
    epi_hidden(smc, d, m0, n0h, lane);
    __syncthreads();
#pragma unroll
    for (int i = 0; i < 16; i++) { d[i][0] = d[i][1] = d[i][2] = d[i][3] = 0.f; }
    run_layer_grp<8>(SB, gb, B1h, B1l, 8192, wn * 2048, 2048, true,
                     Qh + wn * 4096, Ql + wn * 4096, 1024, 0, 1024,
                     d, m0, lane, lt, barid);
    __syncthreads();
    epi_hidden(smc, d, m0, n0h, lane);
    __syncthreads();

    // =========== q final: K-split across groups (4 chunks each) ===========
    {
#pragma unroll
        for (int i = 0; i < 8; i++) { d[i][0] = d[i][1] = d[i][2] = d[i][3] = 0.f; }
#pragma unroll 1
        for (int c = 0; c < 4; c++) {
            CP_WAIT1();
            BARG(barid);
            compute_grp<4>(SB, gb + (c & 1) * 4096u, d, m0, lane, (4 * wn + c) * 32);
            BARG(barid);
            if (c < 2) {
                copy_slice(gb + (c & 1) * 4096u, Qh + (4 * wn + c + 2) * 1024,
                           Ql + (4 * wn + c + 2) * 1024, 1024, lt);
            } else {
                int cc = c - 2;
                copy_slice(gb + (cc & 1) * 4096u, B0h + cc * 8192 + wn * 2048,
                           B0l + cc * 8192 + wn * 2048, 2048, lt);
            }
        }
        __syncthreads();                   // all reads of A done -> AH reusable
        float* part = (float*)(smc + OFF_AH) + wn * 2048;
#pragma unroll
        for (int i = 0; i < 2; i++)
#pragma unroll
            for (int j = 0; j < 4; j++) {
                int n = j * 8 + 2 * (lane & 3);
                int m = m0 + 16 * i + (lane >> 2);
                float* dd = d[i * 4 + j];
                part[m * 32 + n]           = dd[0];
                part[m * 32 + n + 1]       = dd[1];
                part[(m + 8) * 32 + n]     = dd[2];
                part[(m + 8) * 32 + n + 1] = dd[3];
            }
        __syncthreads();
        float* P = (float*)(smc + OFF_AH);
        for (int i = tid; i < 2048; i += NTHREADS) {
            int m = i >> 5, n = i & 31;
            qsm[m * 33 + n] = P[i] + P[2048 + i] + P[4096 + i] + P[6144 + i];
        }
        __syncthreads();
    }

    // =========== PATH 1 (neighbor) ===========
    stage_X(smc, nbr, e0, tid);
    __syncthreads();
#pragma unroll
    for (int i = 0; i < 16; i++) { d[i][0] = d[i][1] = d[i][2] = d[i][3] = 0.f; }
    run_layer_grp<8>(SB, gb, B0h, B0l, 8192, wn * 2048, 2048, true,
                     B1h, B1l, 8192, wn * 2048, 2048, d, m0, lane, lt, barid);
    __syncthreads();
    epi_hidden(smc, d, m0, n0h, lane);
    __syncthreads();
#pragma unroll
    for (int i = 0; i < 16; i++) { d[i][0] = d[i][1] = d[i][2] = d[i][3] = 0.f; }
    run_layer_grp<8>(SB, gb, B1h, B1l, 8192, wn * 2048, 2048, true,
                     Nh, Nl, 3072, wn * 1024, (wn < 3) ? 1024 : 0,
                     d, m0, lane, lt, barid);
    __syncthreads();
    epi_hidden(smc, d, m0, n0h, lane);
    __syncthreads();

    // =========== neighbor final: N=96 [x_n(64) | k(32)], groups 0..2 ======
#pragma unroll
    for (int i = 0; i < 8; i++) { d[i][0] = d[i][1] = d[i][2] = d[i][3] = 0.f; }
    if (wn < 3) {
        run_layer_grp<4>(SB, gb, Nh, Nl, 3072, wn * 1024, 1024, true,
                         (const char*)0, (const char*)0, 0, 0, 0,
                         d, m0, lane, lt, barid);
    }
    __syncthreads();                       // finals done; B region reusable
    if (wn == 2) {                          // k -> ksm
#pragma unroll
        for (int i = 0; i < 2; i++)
#pragma unroll
            for (int j = 0; j < 4; j++) {
                int h = j * 8 + 2 * (lane & 3);
                int m = m0 + 16 * i + (lane >> 2);
                float* dd = d[i * 4 + j];
                ksm[m * 33 + h]           = dd[0];
                ksm[m * 33 + h + 1]       = dd[1];
                ksm[(m + 8) * 33 + h]     = dd[2];
                ksm[(m + 8) * 33 + h + 1] = dd[3];
            }
    } else if (wn < 2) {                    // x_n -> wsm
#pragma unroll
        for (int i = 0; i < 2; i++)
#pragma unroll
            for (int j = 0; j < 4; j++) {
                int cc = wn * 32 + j * 8 + 2 * (lane & 3);
                int m = m0 + 16 * i + (lane >> 2);
                float* dd = d[i * 4 + j];
                wsm[m * 65 + cc]           = dd[0];
                wsm[m * 65 + cc + 1]       = dd[1];
                wsm[(m + 8) * 65 + cc]     = dd[2];
                wsm[(m + 8) * 65 + cc + 1] = dd[3];
            }
    }
    __syncthreads();
    if (tid < TILE) {                       // attention scalar
        float s = 0.f;
#pragma unroll
        for (int h = 0; h < HSZ; h++) s += qsm[tid * 33 + h] * ksm[tid * 33 + h];
        ewsm[tid] = ppr[e0 + tid] / (1.f + expf(-s));
        gid[tid]  = pidx[e0 + tid];
    }
    __syncthreads();
    {   // RLE segmented atomics (ppr_idx sorted): 4 strips x 16 edges x 64 cols
        const int col = tid & 63;
        const int base = (tid >> 6) * 16;
        float acc = 0.f;
        int prev = gid[base];
#pragma unroll
        for (int i = 0; i < 16; i++) {
            int g = gid[base + i];
            if (g != prev) {
                atomicAdd(out + (size_t)prev * NCLS + col, acc);
                acc = 0.f;
                prev = g;
            }
            acc += wsm[(base + i) * 65 + col] * ewsm[base + i];
        }
        atomicAdd(out + (size_t)prev * NCLS + col, acc);
    }
}

// ---------------- launch ----------------
extern "C" void kernel_launch(void* const* d_in, const int* in_sizes, int n_in,
                              void* d_out, int out_size) {
    const float* src  = (const float*)d_in[0];
    const float* nbr  = (const float*)d_in[1];
    const float* ppr  = (const float*)d_in[2];
    const int*   pidx = (const int*)  d_in[3];
    // d_in[4] = neighbor_idx (unused by reference)
    const float* W0   = (const float*)d_in[5];
    const float* W1   = (const float*)d_in[6];
    const float* W2   = (const float*)d_in[7];
    const float* Wqk  = (const float*)d_in[8];
    const float* Wk   = (const float*)d_in[9];
    float* out = (float*)d_out;

    cudaFuncSetAttribute(gnn_main, cudaFuncAttributeMaxDynamicSharedMemorySize,
                         (int)SMEM_REQ);

    prep_w01<<<512, 256>>>(W0, W1);
    prep_wf<<<128, 256>>>(W2, Wqk, Wk);
    zero_out_kernel<<<(out_size + 255) / 256, 256>>>(out, out_size);
    gnn_main<<<NBLK, NTHREADS, SMEM_REQ>>>(src, nbr, ppr, pidx, out);
}

// round 11
// speedup vs baseline: 2.6844x; 1.0013x over previous
#include <cuda_runtime.h>
#include <cuda_bf16.h>
#include <math.h>
#include <stdint.h>

// ---------------- problem constants ----------------
#define E_TOT   400000
#define TILE    64
#define NBLK    (E_TOT / TILE)   // 6250
#define NCLS    64
#define HSZ     32
#define NTHREADS 256

// ---------------- smem layout (from 1024-aligned base) ----------------
#define OFF_AH   0u          // A hi : 64 rows x 512B = 32KB
#define OFF_AL   32768u      // A lo : 32KB
#define OFF_B    65536u      // 4 groups x 2 bufs x 4KB = 32KB
#define OFF_Q    98304u      // q f32 [64][33] = 8448B
#define OFF_EW   106752u     // ew f32 [64]
#define OFF_GID  107008u     // gid int [64]
#define OFF_KSM  65536u      // k  f32 [64][33] (alias over B, post-GEMM)
#define OFF_WSM  74240u      // xn f32 [64][65] (alias over B, post-GEMM)
#define SMEM_REQ (107264u + 1024u)

// ---------------- pre-split, pre-swizzled weights ----------------
// Kc=16 chunks; within chunk, row n (32B): byte n*32 + ((kk*2)^(((n>>2)&1)<<4))
__device__ unsigned short gB0h[65536], gB0l[65536];   // layer0: 16 chunks x 8KB
__device__ unsigned short gB1h[65536], gB1l[65536];   // layer1
__device__ unsigned short gBqh[8192],  gBql[8192];    // q image N=32 (W2@Wqk): 16 x 1KB
__device__ unsigned short gBnh[24576], gBnl[24576];   // final N=96 [W2 | W2@Wk]: 16 x 3KB

// ---------------- helpers ----------------
__device__ __forceinline__ uint32_t smem_u32(const void* p) {
    uint32_t a;
    asm("{ .reg .u64 t; cvta.to.shared.u64 t, %1; cvt.u32.u64 %0, t; }"
        : "=r"(a) : "l"(p));
    return a;
}
__device__ __forceinline__ void split2(float a, float b, uint32_t& hi, uint32_t& lo) {
    uint32_t h;
    asm("cvt.rn.bf16x2.f32 %0, %1, %2;" : "=r"(h) : "f"(b), "f"(a));
    float ha = __uint_as_float(h << 16);
    float hb = __uint_as_float(h & 0xffff0000u);
    asm("cvt.rn.bf16x2.f32 %0, %1, %2;" : "=r"(lo) : "f"(b - hb), "f"(a - ha));
    hi = h;
}
__device__ __forceinline__ void split1(float x, unsigned short& hu, unsigned short& lu) {
    __nv_bfloat16 hb = __float2bfloat16(x);
    hu = *reinterpret_cast<unsigned short*>(&hb);
    float hf = __uint_as_float((uint32_t)hu << 16);
    __nv_bfloat16 lb = __float2bfloat16(x - hf);
    lu = *reinterpret_cast<unsigned short*>(&lb);
}
__device__ __forceinline__ void ldsm4(uint32_t addr, uint32_t& r0, uint32_t& r1,
                                      uint32_t& r2, uint32_t& r3) {
    asm volatile("ldmatrix.sync.aligned.m8n8.x4.shared.b16 {%0,%1,%2,%3}, [%4];"
                 : "=r"(r0), "=r"(r1), "=r"(r2), "=r"(r3) : "r"(addr));
}
__device__ __forceinline__ void mma16816(float* d, const uint32_t* a,
                                         uint32_t b0, uint32_t b1) {
    asm volatile("mma.sync.aligned.m16n8k16.row.col.f32.bf16.bf16.f32 "
                 "{%0,%1,%2,%3}, {%4,%5,%6,%7}, {%8,%9}, {%0,%1,%2,%3};"
                 : "+f"(d[0]), "+f"(d[1]), "+f"(d[2]), "+f"(d[3])
                 : "r"(a[0]), "r"(a[1]), "r"(a[2]), "r"(a[3]), "r"(b0), "r"(b1));
}
__device__ __forceinline__ void cpa16(uint32_t s, const void* g) {
    asm volatile("cp.async.cg.shared.global [%0], [%1], 16;" :: "r"(s), "l"(g));
}
#define CP_COMMIT() asm volatile("cp.async.commit_group;")
#define CP_WAIT1()  asm volatile("cp.async.wait_group 1;" ::: "memory")
#define BARG(id)    asm volatile("bar.sync %0, 64;" :: "r"(id) : "memory")

// A swizzle: row = 512B, conflict-free ldmatrix
__device__ __forceinline__ uint32_t aoff(int row, int kb) {
    return (uint32_t)row * 512u + (uint32_t)(kb ^ ((row & 7) << 4));
}
// B swizzle within slice/chunk: row = 32B
__device__ __forceinline__ uint32_t bxor(int r, int lh) {
    return (uint32_t)r * 32u + (uint32_t)(lh ^ (((r >> 2) & 1) << 4));
}

// ---------------- setup kernels ----------------
__global__ void prep_w01(const float* __restrict__ W0, const float* __restrict__ W1) {
    int idx = blockIdx.x * blockDim.x + threadIdx.x;   // 131072
    int layer = idx >> 16;
    int rem = idx & 65535;
    int k = rem >> 8, n = rem & 255;
    const float* W = layer ? W1 : W0;
    unsigned short hu, lu;
    split1(W[k * 256 + n], hu, lu);
    int c = k >> 4, kk = k & 15;
    uint32_t bp = (uint32_t)c * 8192u + bxor(n, kk * 2);
    (layer ? gB1h : gB0h)[bp >> 1] = hu;
    (layer ? gB1l : gB0l)[bp >> 1] = lu;
}

__global__ void prep_wf(const float* __restrict__ W2, const float* __restrict__ Wqk,
                        const float* __restrict__ Wk) {
    int idx = blockIdx.x * blockDim.x + threadIdx.x;   // 32768
    int k = idx >> 7, n = idx & 127;
    int c = k >> 4, kk = k & 15;
    unsigned short hu, lu;
    if (n < 32) {
        float s = 0.f;
        for (int cc = 0; cc < 64; cc++) s += W2[k * 64 + cc] * Wqk[cc * 32 + n];
        split1(s, hu, lu);
        uint32_t bp = (uint32_t)c * 1024u + bxor(n, kk * 2);
        gBqh[bp >> 1] = hu; gBql[bp >> 1] = lu;
    } else {
        int m = n - 32;
        float v;
        if (m < 64) v = W2[k * 64 + m];
        else {
            float s = 0.f;
            for (int cc = 0; cc < 64; cc++) s += W2[k * 64 + cc] * Wk[cc * 32 + (m - 64)];
            v = s;
        }
        split1(v, hu, lu);
        uint32_t bp = (uint32_t)c * 3072u + bxor(m, kk * 2);
        gBnh[bp >> 1] = hu; gBnl[bp >> 1] = lu;
    }
}

__global__ void zero_out_kernel(float* __restrict__ out, int n) {
    int i = blockIdx.x * blockDim.x + threadIdx.x;
    if (i < n) out[i] = 0.f;
}

// ---------------- GEMM pieces ----------------
// one Kc=16 chunk: D += (Ah+Al)@(Bh+Bl), 3 passes; buf = [hi 2KB | lo 2KB]
template<int NF>
__device__ __forceinline__ void compute_grp(uint32_t SB, uint32_t buf,
                                            float (*d)[4], int m0, int lane, int kbA0) {
    const int lr = lane & 15;
    const int lh = (lane >> 4) * 16;
    const int kbA = kbA0 + lh;
    uint32_t ah[2][4], al[2][4];
#pragma unroll
    for (int i = 0; i < 2; i++) {
        int row = m0 + 16 * i + lr;
        ldsm4(SB + OFF_AH + aoff(row, kbA), ah[i][0], ah[i][1], ah[i][2], ah[i][3]);
        ldsm4(SB + OFF_AL + aoff(row, kbA), al[i][0], al[i][1], al[i][2], al[i][3]);
    }
    uint32_t b[NF][2];
#pragma unroll
    for (int jj = 0; jj < NF / 2; jj++) {
        int r = jj * 16 + lr;
        uint32_t r0, r1, r2, r3;
        ldsm4(buf + bxor(r, lh), r0, r1, r2, r3);
        b[2 * jj][0] = r0; b[2 * jj][1] = r2;
        b[2 * jj + 1][0] = r1; b[2 * jj + 1][1] = r3;
    }
#pragma unroll
    for (int i = 0; i < 2; i++)
#pragma unroll
        for (int j = 0; j < NF; j++) mma16816(d[i * NF + j], ah[i], b[j][0], b[j][1]);
#pragma unroll
    for (int i = 0; i < 2; i++)
#pragma unroll
        for (int j = 0; j < NF; j++) mma16816(d[i * NF + j], al[i], b[j][0], b[j][1]);
#pragma unroll
    for (int jj = 0; jj < NF / 2; jj++) {
        int r = jj * 16 + lr;
        uint32_t r0, r1, r2, r3;
        ldsm4(buf + 2048u + bxor(r, lh), r0, r1, r2, r3);
        b[2 * jj][0] = r0; b[2 * jj][1] = r2;
        b[2 * jj + 1][0] = r1; b[2 * jj + 1][1] = r3;
    }
#pragma unroll
    for (int i = 0; i < 2; i++)
#pragma unroll
        for (int j = 0; j < NF; j++) mma16816(d[i * NF + j], ah[i], b[j][0], b[j][1]);
}

// group copies its own slice (hi+lo) + commit (1 group)
__device__ __forceinline__ void copy_slice(uint32_t dst, const char* srcH,
                                           const char* srcL, int nbytes, int lt) {
    for (int i = lt * 16; i < nbytes; i += 64 * 16) {
        cpa16(dst + i, srcH + i);
        cpa16(dst + 2048u + i, srcL + i);
    }
    CP_COMMIT();
}

// full layer: 16 chunks, group-private double buffer, named barriers.
// pre: chunks 0,1 already committed into buf0,buf1.
// At c=14/15 prefetches next image chunks 0,1 (or empty-commits).
template<int NF>
__device__ void run_layer_grp(uint32_t SB, uint32_t gb,
        const char* gH, const char* gL, int chunkB, int sliceOff, int sliceB,
        bool pre, const char* nxH, const char* nxL, int nxChunkB, int nxSliceOff,
        int nxSliceB, float (*d)[4], int m0, int lane, int lt, int barid) {
    if (!pre) {
        copy_slice(gb,         gH + sliceOff,          gL + sliceOff,          sliceB, lt);
        copy_slice(gb + 4096u, gH + chunkB + sliceOff, gL + chunkB + sliceOff, sliceB, lt);
    }
#pragma unroll 1
    for (int c = 0; c < 16; c++) {
        CP_WAIT1();
        BARG(barid);
        compute_grp<NF>(SB, gb + (c & 1) * 4096u, d, m0, lane, c * 32);
        BARG(barid);
        if (c < 14) {
            copy_slice(gb + (c & 1) * 4096u, gH + (c + 2) * chunkB + sliceOff,
                       gL + (c + 2) * chunkB + sliceOff, sliceB, lt);
        } else if (nxSliceB) {
            int cc = c - 14;
            copy_slice(gb + (cc & 1) * 4096u, nxH + cc * nxChunkB + nxSliceOff,
                       nxL + cc * nxChunkB + nxSliceOff, nxSliceB, lt);
        } else {
            CP_COMMIT();
        }
    }
}

// relu + split -> next layer's A
__device__ __forceinline__ void epi_hidden(char* smc, float (*d)[4], int m0, int n0, int lane) {
#pragma unroll
    for (int i = 0; i < 2; i++)
#pragma unroll
        for (int j = 0; j < 8; j++) {
            float* dd = d[i * 8 + j];
            int n = n0 + j * 8 + 2 * (lane & 3);
            int kb = n * 2;
            int r0 = m0 + 16 * i + (lane >> 2);
            uint32_t hi, lo;
            split2(fmaxf(dd[0], 0.f), fmaxf(dd[1], 0.f), hi, lo);
            *(uint32_t*)(smc + OFF_AH + aoff(r0, kb)) = hi;
            *(uint32_t*)(smc + OFF_AL + aoff(r0, kb)) = lo;
            split2(fmaxf(dd[2], 0.f), fmaxf(dd[3], 0.f), hi, lo);
            *(uint32_t*)(smc + OFF_AH + aoff(r0 + 8, kb)) = hi;
            *(uint32_t*)(smc + OFF_AL + aoff(r0 + 8, kb)) = lo;
        }
}

// load X[64,256] fp32, split, store to A hi/lo
__device__ __forceinline__ void stage_X(char* smc, const float* __restrict__ Xg,
                                        int e0, int tid) {
    int r = tid >> 2, qq = tid & 3;
    const float4* xr = (const float4*)(Xg + (size_t)(e0 + r) * 256) + qq * 16;
#pragma unroll
    for (int j = 0; j < 16; j++) {
        float4 v = xr[j];
        uint32_t h0, l0, h1, l1;
        split2(v.x, v.y, h0, l0);
        split2(v.z, v.w, h1, l1);
        int kb = (qq * 64 + j * 4) * 2;
        uint32_t off = aoff(r, kb);
        *(uint2*)(smc + OFF_AH + off) = make_uint2(h0, h1);
        *(uint2*)(smc + OFF_AL + off) = make_uint2(l0, l1);
    }
}

// ---------------- main fused kernel ----------------
__global__ void __launch_bounds__(NTHREADS, 2)
gnn_main(const float* __restrict__ src, const float* __restrict__ nbr,
         const float* __restrict__ ppr, const int* __restrict__ pidx,
         float* __restrict__ out) {
    extern __shared__ char smraw[];
    char* smc = (char*)(((uintptr_t)smraw + 1023) & ~(uintptr_t)1023);
    const uint32_t SB = smem_u32(smc);
    const int tid = threadIdx.x;
    const int lane = tid & 31;
    const int w = tid >> 5, wm = w >> 2, wn = w & 3;
    const int m0 = wm * 32, n0h = wn * 64;
    const int lt = wm * 32 + lane;        // thread index within wn-group (0..63)
    const int barid = wn + 1;
    const uint32_t gb = SB + OFF_B + (uint32_t)wn * 8192u;
    const int e0 = blockIdx.x * TILE;

    float* qsm  = (float*)(smc + OFF_Q);
    float* ksm  = (float*)(smc + OFF_KSM);
    float* wsm  = (float*)(smc + OFF_WSM);
    float* ewsm = (float*)(smc + OFF_EW);
    int*   gid  = (int*)(smc + OFF_GID);

    const char* B0h = (const char*)gB0h; const char* B0l = (const char*)gB0l;
    const char* B1h = (const char*)gB1h; const char* B1l = (const char*)gB1l;
    const char* Qh  = (const char*)gBqh; const char* Ql  = (const char*)gBql;
    const char* Nh  = (const char*)gBnh; const char* Nl  = (const char*)gBnl;

    float d[16][4];

    // =========== PATH 0 (source) ===========
    stage_X(smc, src, e0, tid);
    __syncthreads();
#pragma unroll
    for (int i = 0; i < 16; i++) { d[i][0] = d[i][1] = d[i][2] = d[i][3] = 0.f; }
    run_layer_grp<8>(SB, gb, B0h, B0l, 8192, wn * 2048, 2048, false,
                     B1h, B1l, 8192, wn * 2048, 2048, d, m0, lane, lt, barid);
    __syncthreads();
    epi_hidden(smc, d, m0, n0h, lane);
    __syncthreads();
#pragma unroll
    for (int i = 0; i < 16; i++) { d[i][0] = d[i][1] = d[i][2] = d[i][3] = 0.f; }
    run_layer_grp<8>(SB, gb, B1h, B1l, 8192, wn * 2048, 2048, true,
                     Qh + wn * 4096, Ql + wn * 4096, 1024, 0, 1024,
                     d, m0, lane, lt, barid);
    __syncthreads();
    epi_hidden(smc, d, m0, n0h, lane);
    __syncthreads();

    // =========== q final: K-split across groups (4 chunks each) ===========
    {
#pragma unroll
        for (int i = 0; i < 8; i++) { d[i][0] = d[i][1] = d[i][2] = d[i][3] = 0.f; }
#pragma unroll 1
        for (int c = 0; c < 4; c++) {
            CP_WAIT1();
            BARG(barid);
            compute_grp<4>(SB, gb + (c & 1) * 4096u, d, m0, lane, (4 * wn + c) * 32);
            BARG(barid);
            if (c < 2) {
                copy_slice(gb + (c & 1) * 4096u, Qh + (4 * wn + c + 2) * 1024,
                           Ql + (4 * wn + c + 2) * 1024, 1024, lt);
            } else {
                int cc = c - 2;
                copy_slice(gb + (cc & 1) * 4096u, B0h + cc * 8192 + wn * 2048,
                           B0l + cc * 8192 + wn * 2048, 2048, lt);
            }
        }
        __syncthreads();                   // all reads of A done -> AH reusable
        float* part = (float*)(smc + OFF_AH) + wn * 2048;
#pragma unroll
        for (int i = 0; i < 2; i++)
#pragma unroll
            for (int j = 0; j < 4; j++) {
                int n = j * 8 + 2 * (lane & 3);
                int m = m0 + 16 * i + (lane >> 2);
                float* dd = d[i * 4 + j];
                part[m * 32 + n]           = dd[0];
                part[m * 32 + n + 1]       = dd[1];
                part[(m + 8) * 32 + n]     = dd[2];
                part[(m + 8) * 32 + n + 1] = dd[3];
            }
        __syncthreads();
        float* P = (float*)(smc + OFF_AH);
        for (int i = tid; i < 2048; i += NTHREADS) {
            int m = i >> 5, n = i & 31;
            qsm[m * 33 + n] = P[i] + P[2048 + i] + P[4096 + i] + P[6144 + i];
        }
        __syncthreads();
    }

    // =========== PATH 1 (neighbor) ===========
    stage_X(smc, nbr, e0, tid);
    __syncthreads();
#pragma unroll
    for (int i = 0; i < 16; i++) { d[i][0] = d[i][1] = d[i][2] = d[i][3] = 0.f; }
    run_layer_grp<8>(SB, gb, B0h, B0l, 8192, wn * 2048, 2048, true,
                     B1h, B1l, 8192, wn * 2048, 2048, d, m0, lane, lt, barid);
    __syncthreads();
    epi_hidden(smc, d, m0, n0h, lane);
    __syncthreads();
#pragma unroll
    for (int i = 0; i < 16; i++) { d[i][0] = d[i][1] = d[i][2] = d[i][3] = 0.f; }
    run_layer_grp<8>(SB, gb, B1h, B1l, 8192, wn * 2048, 2048, true,
                     Nh, Nl, 3072, wn * 1024, (wn < 3) ? 1024 : 0,
                     d, m0, lane, lt, barid);
    __syncthreads();
    epi_hidden(smc, d, m0, n0h, lane);
    __syncthreads();

    // =========== neighbor final: N=96 [x_n(64) | k(32)], groups 0..2 ======
#pragma unroll
    for (int i = 0; i < 8; i++) { d[i][0] = d[i][1] = d[i][2] = d[i][3] = 0.f; }
    if (wn < 3) {
        run_layer_grp<4>(SB, gb, Nh, Nl, 3072, wn * 1024, 1024, true,
                         (const char*)0, (const char*)0, 0, 0, 0,
                         d, m0, lane, lt, barid);
    }
    __syncthreads();                       // finals done; B region reusable
    if (wn == 2) {                          // k -> ksm
#pragma unroll
        for (int i = 0; i < 2; i++)
#pragma unroll
            for (int j = 0; j < 4; j++) {
                int h = j * 8 + 2 * (lane & 3);
                int m = m0 + 16 * i + (lane >> 2);
                float* dd = d[i * 4 + j];
                ksm[m * 33 + h]           = dd[0];
                ksm[m * 33 + h + 1]       = dd[1];
                ksm[(m + 8) * 33 + h]     = dd[2];
                ksm[(m + 8) * 33 + h + 1] = dd[3];
            }
    } else if (wn < 2) {                    // x_n -> wsm
#pragma unroll
        for (int i = 0; i < 2; i++)
#pragma unroll
            for (int j = 0; j < 4; j++) {
                int cc = wn * 32 + j * 8 + 2 * (lane & 3);
                int m = m0 + 16 * i + (lane >> 2);
                float* dd = d[i * 4 + j];
                wsm[m * 65 + cc]           = dd[0];
                wsm[m * 65 + cc + 1]       = dd[1];
                wsm[(m + 8) * 65 + cc]     = dd[2];
                wsm[(m + 8) * 65 + cc + 1] = dd[3];
            }
    }
    __syncthreads();
    if (tid < TILE) {                       // attention scalar
        float s = 0.f;
#pragma unroll
        for (int h = 0; h < HSZ; h++) s += qsm[tid * 33 + h] * ksm[tid * 33 + h];
        ewsm[tid] = ppr[e0 + tid] / (1.f + expf(-s));
        gid[tid]  = pidx[e0 + tid];
    }
    __syncthreads();
    {   // RLE segmented atomics (ppr_idx sorted): 4 strips x 16 edges x 64 cols
        const int col = tid & 63;
        const int base = (tid >> 6) * 16;
        float acc = 0.f;
        int prev = gid[base];
#pragma unroll
        for (int i = 0; i < 16; i++) {
            int g = gid[base + i];
            if (g != prev) {
                atomicAdd(out + (size_t)prev * NCLS + col, acc);
                acc = 0.f;
                prev = g;
            }
            acc += wsm[(base + i) * 65 + col] * ewsm[base + i];
        }
        atomicAdd(out + (size_t)prev * NCLS + col, acc);
    }
}

// ---------------- launch ----------------
extern "C" void kernel_launch(void* const* d_in, const int* in_sizes, int n_in,
                              void* d_out, int out_size) {
    const float* src  = (const float*)d_in[0];
    const float* nbr  = (const float*)d_in[1];
    const float* ppr  = (const float*)d_in[2];
    const int*   pidx = (const int*)  d_in[3];
    // d_in[4] = neighbor_idx (unused by reference)
    const float* W0   = (const float*)d_in[5];
    const float* W1   = (const float*)d_in[6];
    const float* W2   = (const float*)d_in[7];
    const float* Wqk  = (const float*)d_in[8];
    const float* Wk   = (const float*)d_in[9];
    float* out = (float*)d_out;

    cudaFuncSetAttribute(gnn_main, cudaFuncAttributeMaxDynamicSharedMemorySize,
                         (int)SMEM_REQ);

    prep_w01<<<512, 256>>>(W0, W1);
    prep_wf<<<128, 256>>>(W2, Wqk, Wk);
    zero_out_kernel<<<(out_size + 255) / 256, 256>>>(out, out_size);
    gnn_main<<<NBLK, NTHREADS, SMEM_REQ>>>(src, nbr, ppr, pidx, out);
}